// round 13
// baseline (speedup 1.0000x reference)
#include <cuda_runtime.h>
#include <math.h>

// Problem constants
#define Bc 16
#define Ac 3
#define Cc 80
#define Hc 76
#define Wc 76
#define Tc 50
#define Sc (Hc * Wc)            // 5776
#define NCELL (Bc * Ac * Sc)    // 277248
#define NCH 85
#define NT (Bc * Tc)            // 800 targets
#define NSUPW (NCELL / 32)      // 8664 suppression words (exact)

#define TPB 256
#define NWARPS (TPB / 32)
#define NB (NCELL / TPB)        // 1083 blocks, exact (1 cell per thread)

#define BTPB 800                // build threads: one per target
#define KINV 0xFFFFFFFFu

// ---------------------------------------------------------------------------
// Scratch (device globals, no allocation)
// ---------------------------------------------------------------------------
__device__ unsigned g_sup[NSUPW];     // suppression bitmask (noobj=0 cells)
__device__ int      g_nsup;           // popcount of suppression bits
__device__ unsigned g_ekey[NT];       // (cell<<7)|cls, or KINV
__device__ unsigned g_eflag[NT];      // bit0 = winner, bit1 = first (cell,cls)
__device__ float4   g_evals[NT];      // tx,ty,tw,th
__device__ float    g_part[NB];       // per-block noobj-bce partials
__device__ float4   g_epart[NT * 2];  // per-entry: {x,y,w,h},{conf,cls,mask,0}
__device__ unsigned g_done = 0;

// softplus via MUFU intrinsics. bce(sigmoid(x), t) == softplus(x) - t*x
// (reference clip(-100) unreachable for finite normal logits).
__device__ __forceinline__ float softplusf(float x) {
    return fmaxf(x, 0.0f) + __logf(1.0f + __expf(-fabsf(x)));
}

// ---------------------------------------------------------------------------
// Kernel 1: build. One block, 800 threads — one thread per target.
// ---------------------------------------------------------------------------
__global__ void __launch_bounds__(BTPB) yolo_build_kernel(const float* __restrict__ tgt) {
    __shared__ float    s[NT * 5];        // 16 KB staged targets
    __shared__ unsigned skey[NT];
    __shared__ float4   svals[NT];
    __shared__ int      ssup;

    int e = threadIdx.x;                  // target index, 0..799

    // phase A: zero suppression bits + stage targets
    if (e == 0) ssup = 0;
    for (int i = e; i < NSUPW; i += BTPB) g_sup[i] = 0u;
    for (int i = e; i < NT * 5; i += BTPB) s[i] = tgt[i];
    __syncthreads();

    // phase B: per-target compute (fully parallel; RED.OR idempotent)
    {
        // SA = ANCHORS / (608/76) = ANCHORS / 8 (exact in binary)
        const float aw[3] = {1.25f, 2.0f, 4.125f};
        const float ah[3] = {1.625f, 3.75f, 2.875f};

        int b = e / Tc;
        const float* r = s + e * 5;
        float c0 = r[0], c1 = r[1], c2 = r[2], c3 = r[3], c4 = r[4];
        unsigned key = KINV;
        float4 tv = make_float4(0.f, 0.f, 0.f, 0.f);

        if ((c0 + c1 + c2 + c3 + c4) != 0.0f) {      // valid
            int   cls = (int)c0;
            float gx = c1 * (float)Wc;
            float gy = c2 * (float)Hc;
            float gw = c3 * (float)Wc;
            float gh = c4 * (float)Hc;
            int gi = (int)gx;
            int gj = (int)gy;

            float a1 = (gw + 1.0f) * (gh + 1.0f);
            float iou[3];
            int best = 0;
            #pragma unroll
            for (int a = 0; a < 3; a++) {
                float iw = fmaxf(fminf(gw, aw[a]) + 1.0f, 0.0f);
                float ih = fmaxf(fminf(gh, ah[a]) + 1.0f, 0.0f);
                float inter = iw * ih;
                float a2 = (aw[a] + 1.0f) * (ah[a] + 1.0f);
                iou[a] = inter / (a1 + a2 - inter + 1e-16f);
                if (iou[a] > iou[best]) best = a;
            }

            #pragma unroll
            for (int a = 0; a < 3; a++) {
                if (iou[a] > 0.5f) {
                    long long idx = (((long long)(b * Ac + a) * Hc + gj) * Wc + gi);
                    if (idx >= 0 && idx < NCELL) {
                        int ii = (int)idx;
                        atomicOr(&g_sup[ii >> 5], 1u << (ii & 31));
                    }
                }
            }

            if (gj < Hc && gi < Wc) {
                long long cell = (((long long)(b * Ac + best) * Hc + gj) * Wc + gi);
                if (cell >= 0 && cell < NCELL && cls >= 0 && cls < Cc) {
                    key = ((unsigned)cell << 7) | (unsigned)cls;
                    tv.x = gx - (float)gi;
                    tv.y = gy - (float)gj;
                    tv.z = logf(gw / aw[best] + 1e-16f);
                    tv.w = logf(gh / ah[best] + 1e-16f);
                }
            }
        }
        skey[e] = key;
        svals[e] = tv;
    }
    __syncthreads();

    // phase C: winner/first flags (parallel scan) + suppression popcount
    {
        unsigned k = skey[e];
        unsigned fl = 0u;
        if (k != KINV) {
            int base = (e / Tc) * Tc;
            unsigned mycell = k >> 7;
            bool win = true, first = true;
            #pragma unroll 5
            for (int t2 = 0; t2 < Tc; t2++) {
                int e2 = base + t2;
                unsigned k2 = skey[e2];
                bool samecell = (k2 != KINV) && ((k2 >> 7) == mycell);
                if (e2 > e && samecell) win = false;
                if (e2 < e && k2 == k)  first = false;
            }
            fl = (win ? 1u : 0u) | (first ? 2u : 0u);
        }
        g_ekey[e] = k;
        g_eflag[e] = fl;
        g_evals[e] = svals[e];

        int pc = 0;
        for (int i = e; i < NSUPW; i += BTPB) pc += __popc(g_sup[i]);
        if (pc) atomicAdd(&ssup, pc);    // int add: associative, deterministic
    }
    __syncthreads();
    if (e == 0) g_nsup = ssup;
}

// ---------------------------------------------------------------------------
// Kernel 2: main. ONE CELL PER THREAD (277k threads, 1083 blocks) so the
// chip holds ~48 warps/SM and DRAM latency is actually hidden.
//  - Per-thread: conf logit + suppression bit -> noobj bce (single slot).
//  - Per-warp: one masked entry (global warp id < 800, spread over ~100 SMs);
//    class loop lane-split; lane 0 writes two float4 records (fixed mapping
//    => deterministic).
//  - Single-slot block reduce + last-block ticket final combine.
// ---------------------------------------------------------------------------
__global__ void __launch_bounds__(TPB) yolo_main_kernel(
        const float* __restrict__ inp, float* __restrict__ out, int out_size) {
    int i = blockIdx.x * TPB + threadIdx.x;   // cell id, always < NCELL
    int lane = threadIdx.x & 31;
    int wid  = threadIdx.x >> 5;

    // --- per-cell noobj bce ---
    float v0 = 0.0f;
    {
        int g  = i / Sc;
        int hw = i - g * Sc;
        float x4 = inp[(size_t)g * NCH * Sc + 4 * Sc + hw];   // coalesced
        unsigned w = g_sup[i >> 5];                           // uniform per warp
        if (!((w >> (i & 31)) & 1u))
            v0 = softplusf(x4);               // bce(conf, 0)
    }

    // --- per-entry masked terms: one warp per entry ---
    int we = blockIdx.x * NWARPS + wid;
    if (we < NT) {
        unsigned k = g_ekey[we];              // warp-uniform
        float ecls = 0.0f;
        float4 r0 = make_float4(0.f, 0.f, 0.f, 0.f);
        float4 r1 = make_float4(0.f, 0.f, 0.f, 0.f);
        if (k != KINV) {
            unsigned fl = g_eflag[we];
            int cell = (int)(k >> 7);
            int cls  = (int)(k & 127u);
            int g  = cell / Sc;
            int hw = cell - g * Sc;
            const float* base = inp + (size_t)g * NCH * Sc + hw;

            if (fl & 1u) {                    // winner: class softplus sum
                #pragma unroll
                for (int c = lane; c < Cc; c += 32)
                    ecls += softplusf(base[(5 + c) * Sc]);
            }
            if ((fl & 2u) && lane == 1)       // distinct (cell,cls)
                ecls -= base[(5 + cls) * Sc];

            #pragma unroll
            for (int off = 16; off > 0; off >>= 1)
                ecls += __shfl_down_sync(0xffffffffu, ecls, off);

            if ((fl & 1u) && lane == 0) {
                float4 tv = g_evals[we];
                float x0 = base[0];
                float x1 = base[Sc];
                float x2 = base[2 * Sc];
                float x3 = base[3 * Sc];
                float x4 = base[4 * Sc];
                r0.x = softplusf(x0) - tv.x * x0;
                r0.y = softplusf(x1) - tv.y * x1;
                float dw = x2 - tv.z; r0.z = dw * dw;
                float dh = x3 - tv.w; r0.w = dh * dh;
                r1.x = softplusf(-x4);        // bce(conf, 1)
                r1.z = 1.0f;                  // mask count
            }
        } else {
            #pragma unroll
            for (int off = 16; off > 0; off >>= 1)
                ecls += __shfl_down_sync(0xffffffffu, ecls, off);
        }
        if (lane == 0) {
            r1.y = ecls;
            g_epart[we * 2]     = r0;         // one STG.128 each
            g_epart[we * 2 + 1] = r1;
        }
    }

    // --- single-slot deterministic block reduce ---
    #pragma unroll
    for (int off = 16; off > 0; off >>= 1)
        v0 += __shfl_down_sync(0xffffffffu, v0, off);

    __shared__ float swarp[NWARPS];
    if (lane == 0) swarp[wid] = v0;
    __syncthreads();
    if (threadIdx.x == 0) {
        float b = 0.0f;
        #pragma unroll
        for (int w2 = 0; w2 < NWARPS; w2++) b += swarp[w2];
        g_part[blockIdx.x] = b;
    }

    // --- last-block ticket ---
    __shared__ int is_last;
    __threadfence();
    if (threadIdx.x == 0) {
        unsigned t = atomicAdd(&g_done, 1u);
        is_last = (t == NB - 1);
        if (is_last) g_done = 0;              // reset for next replay
    }
    __syncthreads();

    if (is_last) {
        // noobj bce total (fixed order over blocks)
        float a0 = 0.0f;
        for (int j = threadIdx.x; j < NB; j += TPB)
            a0 += __ldcg(&g_part[j]);

        // entry totals (fixed order over entries), float4 loads
        float a[7];
        #pragma unroll
        for (int k = 0; k < 7; k++) a[k] = 0.0f;
        for (int e = threadIdx.x; e < NT; e += TPB) {
            float4 p0 = g_epart[e * 2];
            float4 p1 = g_epart[e * 2 + 1];
            a[0] += p0.x; a[1] += p0.y; a[2] += p0.z; a[3] += p0.w;
            a[4] += p1.x; a[5] += p1.y; a[6] += p1.z;
        }

        #pragma unroll
        for (int off = 16; off > 0; off >>= 1) {
            a0 += __shfl_down_sync(0xffffffffu, a0, off);
            #pragma unroll
            for (int k = 0; k < 7; k++)
                a[k] += __shfl_down_sync(0xffffffffu, a[k], off);
        }
        __shared__ float sfin[NWARPS][8];
        if (lane == 0) {
            sfin[wid][0] = a0;
            #pragma unroll
            for (int k = 0; k < 7; k++) sfin[wid][k + 1] = a[k];
        }
        __syncthreads();

        if (threadIdx.x == 0) {
            float tot[8];
            #pragma unroll
            for (int k = 0; k < 8; k++) {
                float t = 0.0f;
                #pragma unroll
                for (int w2 = 0; w2 < NWARPS; w2++) t += sfin[w2][k];
                tot[k] = t;
            }
            // tot: 0=noobj_bce 1=x 2=y 3=w 4=h 5=conf_obj 6=cls 7=n_mask
            const float N = (float)NCELL;
            float n_m  = tot[7];
            float n_nm = (float)(NCELL - g_nsup);
            float loss_x = tot[1] / N / n_m;
            float loss_y = tot[2] / N / n_m;
            float loss_w = tot[3] / N / n_m;
            float loss_h = tot[4] / N / n_m;
            float loss_conf = tot[5] / N / n_m + 0.5f * tot[0] / N / n_nm;
            float loss_cls  = tot[6] / (n_m * (float)Cc) / n_m;
            float loss = 2.5f * (loss_x + loss_y) + 2.5f * (loss_w + loss_h)
                       + loss_conf + loss_cls;
            float res[7] = {loss, loss_x, loss_y, loss_w, loss_h,
                            loss_conf, loss_cls};
            for (int k = 0; k < 7 && k < out_size; k++) out[k] = res[k];
        }
    }
}

// ---------------------------------------------------------------------------
extern "C" void kernel_launch(void* const* d_in, const int* in_sizes, int n_in,
                              void* d_out, int out_size) {
    const float* inp = (const float*)d_in[0];
    const float* tgt = (const float*)d_in[1];
    if (n_in >= 2 && in_sizes[0] < in_sizes[1]) {   // defensive
        const float* tmp = inp; inp = tgt; tgt = tmp;
    }

    yolo_build_kernel<<<1, BTPB>>>(tgt);
    yolo_main_kernel<<<NB, TPB>>>(inp, (float*)d_out, out_size);
}

// round 14
// speedup vs baseline: 1.1067x; 1.1067x over previous
#include <cuda_runtime.h>
#include <math.h>

// Problem constants
#define Bc 16
#define Ac 3
#define Cc 80
#define Hc 76
#define Wc 76
#define Tc 50
#define Sc (Hc * Wc)            // 5776 (divisible by 4)
#define NCELL (Bc * Ac * Sc)    // 277248
#define NCH 85
#define NT (Bc * Tc)            // 800 targets
#define NSUPW (NCELL / 32)      // 8664 suppression words (exact)

#define TPB 256
#define NWARPS (TPB / 32)
#define NQ (NCELL / 4)          // 69312 float4 cells
#define NB ((NQ + TPB - 1) / TPB)   // 271 blocks (<= one resident wave)

#define KINV 0xFFFFFFFFu

// ---------------------------------------------------------------------------
// Scratch (device globals, no allocation)
// ---------------------------------------------------------------------------
__device__ unsigned g_sup[NSUPW];     // suppression bitmask (noobj=0 cells)
__device__ int      g_nsup;           // popcount of suppression bits
__device__ unsigned g_ekey[NT];       // (cell<<7)|cls, or KINV
__device__ unsigned g_eflag[NT];      // bit0 = winner, bit1 = first (cell,cls)
__device__ float4   g_evals[NT];      // tx,ty,tw,th
__device__ float    g_part[NB * 9];   // per-block partials
__device__ unsigned g_gate = 0;       // build-done flag (reset at end)
__device__ unsigned g_done = 0;       // ticket (reset at end)

// softplus via MUFU intrinsics. bce(sigmoid(x), t) == softplus(x) - t*x
// (reference clip(-100) unreachable for finite normal logits).
__device__ __forceinline__ float softplusf(float x) {
    return fmaxf(x, 0.0f) + __logf(1.0f + __expf(-fabsf(x)));
}

// ---------------------------------------------------------------------------
// Single fused kernel.
//  Block 0: build (256 threads, targets striped) -> fence -> gate release.
//  All blocks: prefetch conf float4 BEFORE the gate (overlaps build with
//  DRAM latency), then R11-style main: 4 cells/thread noobj bce + one warp
//  per entry (blocks 1..100), 9-slot deterministic reduce, last-block ticket.
//  Launch bounds (TPB,2) => <=128 regs => >=2 blocks/SM => all 271 blocks
//  co-resident => spin-gate is safe.
// ---------------------------------------------------------------------------
__global__ void __launch_bounds__(TPB, 2) yolo_fused_kernel(
        const float* __restrict__ inp, const float* __restrict__ tgt,
        float* __restrict__ out, int out_size) {
    int tid  = threadIdx.x;
    int lane = tid & 31;
    int wid  = tid >> 5;
    int i4   = blockIdx.x * TPB + tid;

    // ---- conf prefetch (independent of build) ----
    float4 c4 = make_float4(0.f, 0.f, 0.f, 0.f);
    int cell0 = 0;
    if (i4 < NQ) {
        cell0 = i4 * 4;
        int g  = cell0 / Sc;
        int hw = cell0 - g * Sc;            // multiple of 4 within channel
        c4 = *reinterpret_cast<const float4*>(
            inp + (size_t)g * NCH * Sc + 4 * Sc + hw);
    }

    __shared__ unsigned skey[NT];           // 3.2 KB (block 0 uses it)

    if (blockIdx.x == 0) {
        // ================= BUILD (256 threads) =================
        for (int i = tid; i < NSUPW; i += TPB) g_sup[i] = 0u;
        __syncthreads();                    // zeroing visible before atomics

        // SA = ANCHORS / (608/76) = ANCHORS / 8 (exact in binary)
        const float aw[3] = {1.25f, 2.0f, 4.125f};
        const float ah[3] = {1.625f, 3.75f, 2.875f};

        for (int e = tid; e < NT; e += TPB) {
            int b = e / Tc;
            const float* r = tgt + e * 5;
            float c0 = r[0], c1 = r[1], c2 = r[2], c3 = r[3], cc4 = r[4];
            unsigned key = KINV;
            float4 tv = make_float4(0.f, 0.f, 0.f, 0.f);

            if ((c0 + c1 + c2 + c3 + cc4) != 0.0f) {   // valid
                int   cls = (int)c0;
                float gx = c1 * (float)Wc;
                float gy = c2 * (float)Hc;
                float gw = c3 * (float)Wc;
                float gh = cc4 * (float)Hc;
                int gi = (int)gx;
                int gj = (int)gy;

                // IoU vs anchors (+1 shift), first-max-wins argmax
                float a1 = (gw + 1.0f) * (gh + 1.0f);
                float iou[3];
                int best = 0;
                #pragma unroll
                for (int a = 0; a < 3; a++) {
                    float iw = fmaxf(fminf(gw, aw[a]) + 1.0f, 0.0f);
                    float ih = fmaxf(fminf(gh, ah[a]) + 1.0f, 0.0f);
                    float inter = iw * ih;
                    float a2 = (aw[a] + 1.0f) * (ah[a] + 1.0f);
                    iou[a] = inter / (a1 + a2 - inter + 1e-16f);
                    if (iou[a] > iou[best]) best = a;
                }

                // noobj suppression (idempotent RED.OR, drop-mode bounds)
                #pragma unroll
                for (int a = 0; a < 3; a++) {
                    if (iou[a] > 0.5f) {
                        long long idx = (((long long)(b * Ac + a) * Hc + gj) * Wc + gi);
                        if (idx >= 0 && idx < NCELL) {
                            int ii = (int)idx;
                            atomicOr(&g_sup[ii >> 5], 1u << (ii & 31));
                        }
                    }
                }

                // positive assignment (ok = valid & gj<H & gi<W; drop bounds)
                if (gj < Hc && gi < Wc) {
                    long long cell = (((long long)(b * Ac + best) * Hc + gj) * Wc + gi);
                    if (cell >= 0 && cell < NCELL && cls >= 0 && cls < Cc) {
                        key = ((unsigned)cell << 7) | (unsigned)cls;
                        tv.x = gx - (float)gi;
                        tv.y = gy - (float)gj;
                        tv.z = logf(gw / aw[best] + 1e-16f);
                        tv.w = logf(gh / ah[best] + 1e-16f);
                    }
                }
            }
            skey[e] = key;
            g_evals[e] = tv;                // single writer per e
        }
        __syncthreads();                    // skey + atomics visible in block

        // winner/first flags (order-free parallel scan) + popcount
        __shared__ int ssup;
        if (tid == 0) ssup = 0;
        __syncthreads();

        for (int e = tid; e < NT; e += TPB) {
            unsigned k = skey[e];
            unsigned fl = 0u;
            if (k != KINV) {
                int base = (e / Tc) * Tc;
                unsigned mycell = k >> 7;
                bool win = true, first = true;
                #pragma unroll 5
                for (int t2 = 0; t2 < Tc; t2++) {
                    int e2 = base + t2;
                    unsigned k2 = skey[e2];
                    bool samecell = (k2 != KINV) && ((k2 >> 7) == mycell);
                    if (e2 > e && samecell) win = false;
                    if (e2 < e && k2 == k)  first = false;
                }
                fl = (win ? 1u : 0u) | (first ? 2u : 0u);
            }
            g_ekey[e] = k;
            g_eflag[e] = fl;
        }
        {
            int pc = 0;
            for (int i = tid; i < NSUPW; i += TPB) pc += __popc(g_sup[i]);
            if (pc) atomicAdd(&ssup, pc);   // int add: deterministic
        }
        __syncthreads();
        if (tid == 0) {
            g_nsup = ssup;
            __threadfence();                // build writes -> L2
            *(volatile unsigned*)&g_gate = 1u;   // release gate
        }
        __syncthreads();
    } else {
        // ---- wait for build (one spinner per block; loads already issued) ----
        if (tid == 0) {
            while (*(volatile unsigned*)&g_gate == 0u) __nanosleep(32);
        }
        __syncthreads();
    }

    // ================= MAIN (R11 structure) =================
    float v[9];
    #pragma unroll
    for (int k = 0; k < 9; k++) v[k] = 0.0f;

    // per-cell noobj bce, 4 cells/thread
    if (i4 < NQ) {
        unsigned w  = g_sup[cell0 >> 5];
        unsigned sh = (unsigned)cell0 & 31u;
        float cj[4] = {c4.x, c4.y, c4.z, c4.w};
        #pragma unroll
        for (int j = 0; j < 4; j++) {
            if (!((w >> (sh + j)) & 1u)) {
                v[0] += softplusf(cj[j]);       // bce(conf, 0)
            }
        }
    }

    // per-entry masked terms: one warp per entry, blocks 1..100
    if (blockIdx.x >= 1) {
        int we = (blockIdx.x - 1) * NWARPS + wid;
        if (we < NT) {
            unsigned k = g_ekey[we];            // warp-uniform
            if (k != KINV) {
                unsigned fl = g_eflag[we];
                int cell = (int)(k >> 7);
                int cls  = (int)(k & 127u);
                int g  = cell / Sc;
                int hw = cell - g * Sc;
                const float* base = inp + (size_t)g * NCH * Sc + hw;

                if (fl & 1u) {                  // winner: class softplus sum
                    #pragma unroll
                    for (int c = lane; c < Cc; c += 32)
                        v[7] += softplusf(base[(5 + c) * Sc]);

                    if (lane == 0) {
                        float4 tv = g_evals[we];
                        float x0 = base[0];
                        float x1 = base[Sc];
                        float x2 = base[2 * Sc];
                        float x3 = base[3 * Sc];
                        float x4 = base[4 * Sc];
                        v[2] += softplusf(x0) - tv.x * x0;
                        v[3] += softplusf(x1) - tv.y * x1;
                        float dw = x2 - tv.z; v[4] += dw * dw;
                        float dh = x3 - tv.w; v[5] += dh * dh;
                        v[6] += softplusf(-x4); // bce(conf, 1)
                        v[8] += 1.0f;
                    }
                }
                if ((fl & 2u) && lane == 1)     // distinct (cell,cls)
                    v[7] -= base[(5 + cls) * Sc];
            }
        }
    }

    // noobj count from suppression popcount: derive later (build stored it)

    // ---- deterministic 9-slot block reduce ----
    #pragma unroll
    for (int k = 0; k < 9; k++)
        #pragma unroll
        for (int off = 16; off > 0; off >>= 1)
            v[k] += __shfl_down_sync(0xffffffffu, v[k], off);

    __shared__ float swarp[NWARPS][9];
    if (lane == 0)
        #pragma unroll
        for (int k = 0; k < 9; k++) swarp[wid][k] = v[k];
    __syncthreads();

    if (wid == 0) {
        float a[9];
        #pragma unroll
        for (int k = 0; k < 9; k++)
            a[k] = (lane < NWARPS) ? swarp[lane][k] : 0.0f;
        #pragma unroll
        for (int k = 0; k < 9; k++)
            #pragma unroll
            for (int off = 4; off > 0; off >>= 1)
                a[k] += __shfl_down_sync(0xffffffffu, a[k], off);
        if (lane == 0)
            #pragma unroll
            for (int k = 0; k < 9; k++) g_part[blockIdx.x * 9 + k] = a[k];
    }

    // ---- last-block ticket ----
    __shared__ int is_last;
    __threadfence();
    if (tid == 0) {
        unsigned t = atomicAdd(&g_done, 1u);
        is_last = (t == NB - 1);
    }
    __syncthreads();

    if (is_last) {
        float a[9];
        #pragma unroll
        for (int k = 0; k < 9; k++) a[k] = 0.0f;
        for (int j = tid; j < NB; j += TPB)
            #pragma unroll
            for (int k = 0; k < 9; k++) a[k] += __ldcg(&g_part[j * 9 + k]);

        #pragma unroll
        for (int k = 0; k < 9; k++)
            #pragma unroll
            for (int off = 16; off > 0; off >>= 1)
                a[k] += __shfl_down_sync(0xffffffffu, a[k], off);
        if (lane == 0)
            #pragma unroll
            for (int k = 0; k < 9; k++) swarp[wid][k] = a[k];
        __syncthreads();

        if (tid == 0) {
            float tot[9];
            #pragma unroll
            for (int k = 0; k < 9; k++) {
                float t = 0.0f;
                #pragma unroll
                for (int w2 = 0; w2 < NWARPS; w2++) t += swarp[w2][k];
                tot[k] = t;
            }
            // slots: 0=noobj_bce 2=x 3=y 4=w 5=h 6=conf_obj 7=cls 8=n_mask
            const float N = (float)NCELL;
            float n_m  = tot[8];
            float n_nm = (float)(NCELL - g_nsup);
            float loss_x = tot[2] / N / n_m;
            float loss_y = tot[3] / N / n_m;
            float loss_w = tot[4] / N / n_m;
            float loss_h = tot[5] / N / n_m;
            float loss_conf = tot[6] / N / n_m + 0.5f * tot[0] / N / n_nm;
            float loss_cls  = tot[7] / (n_m * (float)Cc) / n_m;
            float loss = 2.5f * (loss_x + loss_y) + 2.5f * (loss_w + loss_h)
                       + loss_conf + loss_cls;
            float res[7] = {loss, loss_x, loss_y, loss_w, loss_h,
                            loss_conf, loss_cls};
            for (int k = 0; k < 7 && k < out_size; k++) out[k] = res[k];

            // reset gate + ticket for the next graph replay
            *(volatile unsigned*)&g_done = 0u;
            *(volatile unsigned*)&g_gate = 0u;
        }
    }
}

// ---------------------------------------------------------------------------
extern "C" void kernel_launch(void* const* d_in, const int* in_sizes, int n_in,
                              void* d_out, int out_size) {
    const float* inp = (const float*)d_in[0];
    const float* tgt = (const float*)d_in[1];
    if (n_in >= 2 && in_sizes[0] < in_sizes[1]) {   // defensive
        const float* tmp = inp; inp = tgt; tgt = tmp;
    }

    yolo_fused_kernel<<<NB, TPB>>>(inp, tgt, (float*)d_out, out_size);
}